// round 2
// baseline (speedup 1.0000x reference)
#include <cuda_runtime.h>
#include <math.h>

// Problem constants (from reference): T=70, B=64, V=10000, E=512, H=1024, L=2
#define T_  70
#define B_  64
#define V_  10000
#define E_  512
#define H_  1024
#define MTOT (T_ * B_)   // 4480 rows (= 35 * 128)

// Scratch (allocation-free rule: __device__ globals)
__device__ float g_X0[(size_t)MTOT * H_];  // emb @ Wx0^T + bh0
__device__ float g_H0[(size_t)MTOT * H_];  // layer-0 hidden states, all t
__device__ float g_X1[(size_t)MTOT * H_];  // H0 @ Wx1^T + bh1
__device__ float g_H1[(size_t)MTOT * H_];  // layer-1 hidden states, all t

// ---------------------------------------------------------------------------
// Tiled SGEMM (NT layout): C[m, n] = sum_k Arow(m)[k] * B[n, k] + bias[n]
//   A: [M, K] row-major, optionally gathered: Arow(m) = A + gidx[m]*K
//   B: [N, K] row-major (nn.Linear weight layout [out, in])
//   Tile 128x128, Kc=8, double-buffered smem, 8x8 per thread, 256 threads.
//   M and K must be multiples of 128 / 8 (true for all call sites).
//   N handled with guards (N=10000 is 8-aligned so fragments never straddle).
// ---------------------------------------------------------------------------
__global__ __launch_bounds__(256) void sgemm_tn(
    const float* __restrict__ A, const float* __restrict__ Bm,
    const float* __restrict__ bias, float* __restrict__ C,
    const int* __restrict__ gidx, int M, int N, int K, int ldc)
{
    __shared__ __align__(16) float As[2][8][132];
    __shared__ __align__(16) float Bs[2][8][132];

    const int t  = threadIdx.x;
    const int tx = t & 15;        // 0..15  (N fragment)
    const int ty = t >> 4;        // 0..15  (M fragment)
    const int m0 = blockIdx.y * 128;
    const int n0 = blockIdx.x * 128;

    // Global-load mapping: each thread loads one float4 of A and one of B per chunk
    const int lrow = t >> 1;            // 0..127 (tile row)
    const int lk   = (t & 1) * 4;       // 0 or 4 (k offset within chunk)

    const int am = m0 + lrow;
    const float* Aptr = gidx ? (A + (size_t)gidx[am] * K)
                             : (A + (size_t)am * K);
    const int bn = n0 + lrow;
    const bool bok = (bn < N);
    const float* Bptr = Bm + (size_t)bn * K;

    // Preload chunk 0
    float4 av = *(const float4*)(Aptr + lk);
    float4 bv = bok ? *(const float4*)(Bptr + lk) : make_float4(0.f, 0.f, 0.f, 0.f);
    As[0][lk + 0][lrow] = av.x; As[0][lk + 1][lrow] = av.y;
    As[0][lk + 2][lrow] = av.z; As[0][lk + 3][lrow] = av.w;
    Bs[0][lk + 0][lrow] = bv.x; Bs[0][lk + 1][lrow] = bv.y;
    Bs[0][lk + 2][lrow] = bv.z; Bs[0][lk + 3][lrow] = bv.w;
    __syncthreads();

    float acc[8][8];
    #pragma unroll
    for (int i = 0; i < 8; i++)
        #pragma unroll
        for (int j = 0; j < 8; j++) acc[i][j] = 0.f;

    const int nk = K >> 3;
    for (int kt = 0; kt < nk; kt++) {
        const int buf = kt & 1;
        float4 a2, b2;
        const bool more = (kt + 1 < nk);
        if (more) {
            const int ko = (kt + 1) * 8 + lk;
            a2 = *(const float4*)(Aptr + ko);
            b2 = bok ? *(const float4*)(Bptr + ko) : make_float4(0.f, 0.f, 0.f, 0.f);
        }

        #pragma unroll
        for (int k = 0; k < 8; k++) {
            float a[8], b[8];
            *(float4*)(a)     = *(const float4*)&As[buf][k][ty * 8];
            *(float4*)(a + 4) = *(const float4*)&As[buf][k][ty * 8 + 4];
            *(float4*)(b)     = *(const float4*)&Bs[buf][k][tx * 8];
            *(float4*)(b + 4) = *(const float4*)&Bs[buf][k][tx * 8 + 4];
            #pragma unroll
            for (int i = 0; i < 8; i++)
                #pragma unroll
                for (int j = 0; j < 8; j++)
                    acc[i][j] += a[i] * b[j];
        }

        if (more) {
            const int nb = buf ^ 1;
            As[nb][lk + 0][lrow] = a2.x; As[nb][lk + 1][lrow] = a2.y;
            As[nb][lk + 2][lrow] = a2.z; As[nb][lk + 3][lrow] = a2.w;
            Bs[nb][lk + 0][lrow] = b2.x; Bs[nb][lk + 1][lrow] = b2.y;
            Bs[nb][lk + 2][lrow] = b2.z; Bs[nb][lk + 3][lrow] = b2.w;
        }
        __syncthreads();
    }

    // Epilogue: bias + store. N is 8-aligned, fragment is 8 wide & 8-aligned,
    // so a single per-thread guard suffices.
    const int nfrag = n0 + tx * 8;
    if (nfrag < N) {
        float bb[8];
        #pragma unroll
        for (int j = 0; j < 8; j++) bb[j] = bias ? bias[nfrag + j] : 0.f;
        #pragma unroll
        for (int i = 0; i < 8; i++) {
            const int m = m0 + ty * 8 + i;
            float4 c0 = make_float4(acc[i][0] + bb[0], acc[i][1] + bb[1],
                                    acc[i][2] + bb[2], acc[i][3] + bb[3]);
            float4 c1 = make_float4(acc[i][4] + bb[4], acc[i][5] + bb[5],
                                    acc[i][6] + bb[6], acc[i][7] + bb[7]);
            float* crow = C + (size_t)m * ldc + nfrag;
            *(float4*)(crow)     = c0;
            *(float4*)(crow + 4) = c1;
        }
    }
}

// ---------------------------------------------------------------------------
// One recurrence step: hout[b, n] = tanh(X[b, n] + sum_k hprev[b, k] * W[n, k])
//   X, hprev, hout: [B=64, H=1024]; W: [H, H] row-major [out, in].
//   Grid = H/8 = 128 blocks, 256 threads. Thread -> (m = tid>>2, nloc = tid&3),
//   computes outputs (m, nbase+nloc) and (m, nbase+nloc+4).
//   h-row float4 loads are 4-way broadcast within a warp (one LDG.128 serves
//   8 distinct rows). Per warp per step: 768 LDG.128 + 2048 FFMA -> LSU-bound.
// ---------------------------------------------------------------------------
__global__ __launch_bounds__(256) void rnn_step(
    const float* __restrict__ X, const float* __restrict__ hprev,
    const float* __restrict__ W, float* __restrict__ hout)
{
    const int nbase = blockIdx.x * 8;
    const int nloc  = threadIdx.x & 3;
    const int m     = threadIdx.x >> 2;          // 0..63
    const int n0 = nbase + nloc;
    const int n1 = nbase + nloc + 4;

    const float4* h4  = (const float4*)(hprev + (size_t)m  * H_);
    const float4* w04 = (const float4*)(W     + (size_t)n0 * H_);
    const float4* w14 = (const float4*)(W     + (size_t)n1 * H_);

    // Hoist the X reads so their latency hides under the dot product.
    const float x0 = X[(size_t)m * H_ + n0];
    const float x1 = X[(size_t)m * H_ + n1];

    float acc0 = 0.f, acc1 = 0.f;
    #pragma unroll 8
    for (int k = 0; k < H_ / 4; k++) {
        const float4 h = h4[k];
        const float4 a = w04[k];
        const float4 b = w14[k];
        acc0 += h.x * a.x + h.y * a.y + h.z * a.z + h.w * a.w;
        acc1 += h.x * b.x + h.y * b.y + h.z * b.z + h.w * b.w;
    }
    hout[(size_t)m * H_ + n0] = tanhf(x0 + acc0);
    hout[(size_t)m * H_ + n1] = tanhf(x1 + acc1);
}

// h_final = [H0[T-1], H1[T-1]]  -> d_out tail
__global__ void copy_final(const float* __restrict__ H0,
                           const float* __restrict__ H1,
                           float* __restrict__ dst)
{
    const int i = blockIdx.x * blockDim.x + threadIdx.x;
    const int n = B_ * H_;
    if (i < n)          dst[i] = H0[(size_t)(T_ - 1) * n + i];
    else if (i < 2 * n) dst[i] = H1[(size_t)(T_ - 1) * n + (i - n)];
}

extern "C" void kernel_launch(void* const* d_in, const int* in_sizes, int n_in,
                              void* d_out, int out_size)
{
    (void)in_sizes; (void)n_in; (void)out_size;
    const int*   inputs = (const int*)  d_in[0];   // [T, B] int32
    const float* hidden = (const float*)d_in[1];   // [L, B, H]
    const float* emb    = (const float*)d_in[2];   // [V, E]
    const float* Wx0    = (const float*)d_in[3];   // [H, E]
    const float* Wx1    = (const float*)d_in[4];   // [H, H]
    const float* Wh0    = (const float*)d_in[5];   // [H, H]
    const float* bh0    = (const float*)d_in[6];   // [H]
    const float* Wh1    = (const float*)d_in[7];   // [H, H]
    const float* bh1    = (const float*)d_in[8];   // [H]
    const float* Wy     = (const float*)d_in[9];   // [V, H]
    const float* by     = (const float*)d_in[10];  // [V]
    float* out = (float*)d_out;                    // [T*B*V logits][L*B*H h_final]

    float *X0, *H0, *X1, *H1;
    cudaGetSymbolAddress((void**)&X0, g_X0);
    cudaGetSymbolAddress((void**)&H0, g_H0);
    cudaGetSymbolAddress((void**)&X1, g_X1);
    cudaGetSymbolAddress((void**)&H1, g_H1);

    const dim3 tb(256);
    const size_t BH = (size_t)B_ * H_;

    // Phase A: X0[t,b,:] = emb[inputs[t,b],:] @ Wx0^T + bh0   (batched over all t)
    sgemm_tn<<<dim3(H_ / 128, MTOT / 128), tb>>>(
        emb, Wx0, bh0, X0, inputs, MTOT, H_, E_, H_);

    // Phase B: layer-0 recurrence (independent of layer 1)
    for (int t = 0; t < T_; t++) {
        const float* hp = (t == 0) ? hidden : (H0 + (size_t)(t - 1) * BH);
        rnn_step<<<H_ / 8, 256>>>(X0 + (size_t)t * BH, hp, Wh0, H0 + (size_t)t * BH);
    }

    // Phase C: X1 = H0 @ Wx1^T + bh1   (batched over all t)
    sgemm_tn<<<dim3(H_ / 128, MTOT / 128), tb>>>(
        H0, Wx1, bh1, X1, nullptr, MTOT, H_, H_, H_);

    // Phase D: layer-1 recurrence
    for (int t = 0; t < T_; t++) {
        const float* hp = (t == 0) ? (hidden + BH) : (H1 + (size_t)(t - 1) * BH);
        rnn_step<<<H_ / 8, 256>>>(X1 + (size_t)t * BH, hp, Wh1, H1 + (size_t)t * BH);
    }

    // Phase E: logits = H1 @ Wy^T + by  -> out[0 : T*B*V]
    sgemm_tn<<<dim3((V_ + 127) / 128, MTOT / 128), tb>>>(
        H1, Wy, by, out, nullptr, MTOT, V_, H_, V_);

    // Phase F: h_final tail
    copy_final<<<(2 * (int)BH + 255) / 256, 256>>>(H0, H1, out + (size_t)MTOT * V_);
}

// round 3
// speedup vs baseline: 2.9644x; 2.9644x over previous
#include <cuda_runtime.h>
#include <math.h>

// Problem constants: T=70, B=64, V=10000, E=512, H=1024, L=2
#define T_  70
#define B_  64
#define V_  10000
#define E_  512
#define H_  1024
#define MTOT (T_ * B_)          // 4480 = 35 * 128
#define BH   (B_ * H_)          // 65536

// Scratch (__device__ globals: allocation-free rule)
__device__ float g_X0[(size_t)MTOT * H_];
__device__ float g_H0[(size_t)MTOT * H_];
__device__ float g_X1[(size_t)MTOT * H_];
__device__ float g_H1[(size_t)MTOT * H_];
__device__ float g_P[(size_t)16 * BH];     // k-split partials [16][64][1024]
__device__ unsigned g_bar;                  // grid-barrier counter

__global__ void bar_init() { g_bar = 0; }

// ---------------------------------------------------------------------------
// Software grid barrier: 128 co-resident blocks. Monotonic counter, absolute
// targets; counter zeroed by bar_init before each persistent launch.
// ---------------------------------------------------------------------------
__device__ __forceinline__ void gridbar(unsigned target) {
    __threadfence();
    __syncthreads();
    if (threadIdx.x == 0) {
        atomicAdd(&g_bar, 1u);
        while (atomicAdd(&g_bar, 0u) < target) __nanosleep(64);
    }
    __syncthreads();
}

// P-column permutation: compute threads store their 8 n's (n = j*8 + tn,
// interleaved to dodge smem bank conflicts) at contiguous p-index tn*8 + j.
__device__ __forceinline__ int pidx(int n) {
    const int nl = n & 63;
    return (n & ~63) | ((nl & 7) << 3) | (nl >> 3);
}

// ---------------------------------------------------------------------------
// Persistent recurrence: one launch runs all T=70 steps of one layer.
// Grid 128 blocks x 256 threads. Block (ntile = bid>>3, ks = bid&7) owns
// W rows [ntile*64, +64) x cols [ks*128, +128) resident in SMEM for the whole
// kernel. Per step: partial C[64m x 64n] over 128 k -> gmem partials (16 of
// them incl. the in-block k-half split) -> barrier -> reduce+X+tanh -> barrier.
// ---------------------------------------------------------------------------
__global__ __launch_bounds__(256) void rnn_layer(
    const float* __restrict__ X, const float* __restrict__ hinit,
    const float* __restrict__ W, float* __restrict__ Hall)
{
    __shared__ float Ws[64][132];

    const int tid   = threadIdx.x;
    const int bid   = blockIdx.x;
    const int ntile = bid >> 3;           // 0..15
    const int ks    = bid & 7;            // 0..7
    const int n0    = ntile * 64;
    const int kb    = ks * 128;

    // Load W slice once (resident across all steps)
    {
        const int r  = tid >> 2;          // 0..63
        const int q4 = (tid & 3) * 4;     // 0,4,8,12
        #pragma unroll
        for (int s = 0; s < 8; s++) {
            const int c = q4 + s * 16;
            *(float4*)&Ws[r][c] = *(const float4*)&W[(size_t)(n0 + r) * H_ + kb + c];
        }
    }
    __syncthreads();

    const int kh   = tid >> 7;            // k-half 0/1 (64 k each)
    const int t7   = tid & 127;
    const int tm   = t7 & 15;             // m-group (4 rows)
    const int tn   = t7 >> 4;             // 0..7
    const int m0   = tm * 4;
    const int kloc = kh * 64;
    float* Pp = g_P + (size_t)(ks * 2 + kh) * BH;

    const int e  = bid * 512 + tid * 2;   // reduce mapping
    const int rm = e >> 10;
    const int rn = e & 1023;
    const int pi0 = pidx(rn), pi1 = pidx(rn + 1);

    unsigned target = 0;

    for (int t = 0; t < T_; t++) {
        const float* hp = t ? (Hall + (size_t)(t - 1) * BH) : hinit;

        float acc[4][8];
        #pragma unroll
        for (int i = 0; i < 4; i++)
            #pragma unroll
            for (int j = 0; j < 8; j++) acc[i][j] = 0.f;

        #pragma unroll 4
        for (int kq = 0; kq < 16; kq++) {
            const int kl = kloc + kq * 4;
            const int k  = kb + kl;
            float4 hv[4];
            #pragma unroll
            for (int i = 0; i < 4; i++)
                hv[i] = *(const float4*)&hp[(size_t)(m0 + i) * H_ + k];
            #pragma unroll
            for (int j = 0; j < 8; j++) {
                const float4 wv = *(const float4*)&Ws[j * 8 + tn][kl];
                #pragma unroll
                for (int i = 0; i < 4; i++)
                    acc[i][j] += hv[i].x * wv.x + hv[i].y * wv.y
                               + hv[i].z * wv.z + hv[i].w * wv.w;
            }
        }

        // Store partial (permuted n layout -> contiguous float4s)
        #pragma unroll
        for (int i = 0; i < 4; i++) {
            float* dst = Pp + (size_t)(m0 + i) * H_ + n0 + tn * 8;
            *(float4*)dst       = make_float4(acc[i][0], acc[i][1], acc[i][2], acc[i][3]);
            *(float4*)(dst + 4) = make_float4(acc[i][4], acc[i][5], acc[i][6], acc[i][7]);
        }

        target += 128; gridbar(target);

        // Reduce 16 partials + X, tanh, write h_t (L2-coherent reads of P)
        {
            const float* Xt = X + (size_t)t * BH;
            float s0 = Xt[e], s1 = Xt[e + 1];
            const size_t base = (size_t)rm * H_;
            #pragma unroll
            for (int j = 0; j < 16; j++) {
                const float* pj = g_P + (size_t)j * BH + base;
                s0 += __ldcg(pj + pi0);
                s1 += __ldcg(pj + pi1);
            }
            float* Ht = Hall + (size_t)t * BH;
            Ht[e]     = tanhf(s0);
            Ht[e + 1] = tanhf(s1);
        }

        target += 128; gridbar(target);
    }
}

// ---------------------------------------------------------------------------
// TF32 tensor-core GEMM: C[m,n] = A[m,:] . B[n,:] + bias[n]
// A: [M,K] row-major (optional gather), B: [N,K] row-major, fp32 accum.
// Block 128x128, kc=16 double-buffered, 8 warps (4m x 2n), warp 32m x 64n,
// mma.sync.m16n8k8.tf32. Smem row stride 20 -> conflict-free frag LDS.
// ---------------------------------------------------------------------------
__device__ __forceinline__ unsigned f2tf(float x) {
    unsigned r; asm("cvt.rna.tf32.f32 %0, %1;" : "=r"(r) : "f"(x)); return r;
}
__device__ __forceinline__ void mma_tf32(float c[4], const unsigned a[4], const unsigned b[2]) {
    asm volatile(
        "mma.sync.aligned.m16n8k8.row.col.f32.tf32.tf32.f32 "
        "{%0,%1,%2,%3}, {%4,%5,%6,%7}, {%8,%9}, {%0,%1,%2,%3};\n"
        : "+f"(c[0]), "+f"(c[1]), "+f"(c[2]), "+f"(c[3])
        : "r"(a[0]), "r"(a[1]), "r"(a[2]), "r"(a[3]), "r"(b[0]), "r"(b[1]));
}
__device__ __forceinline__ uint4 cvt4(float4 v) {
    return make_uint4(f2tf(v.x), f2tf(v.y), f2tf(v.z), f2tf(v.w));
}

__global__ __launch_bounds__(256, 2) void gemm_tf32(
    const float* __restrict__ A, const float* __restrict__ Bm,
    const float* __restrict__ bias, float* __restrict__ C,
    const int* __restrict__ gidx, int N, int K, int ldc)
{
    __shared__ unsigned As[2][128][20];
    __shared__ unsigned Bs[2][128][20];

    const int tid  = threadIdx.x;
    const int lane = tid & 31, warp = tid >> 5;
    const int wm = warp >> 1, wn = warp & 1;
    const int gid = lane >> 2, tig = lane & 3;
    const int bm = blockIdx.y * 128, bn = blockIdx.x * 128;

    // Loader: thread covers rows lr and lr+64, k-quad lq within the stage
    const int lr = tid >> 2;
    const int lq = (tid & 3) * 4;
    const float* Ar0 = A + (size_t)(gidx ? gidx[bm + lr]      : (bm + lr))      * K;
    const float* Ar1 = A + (size_t)(gidx ? gidx[bm + lr + 64] : (bm + lr + 64)) * K;
    const int nr0 = bn + lr, nr1 = bn + lr + 64;
    const bool bok0 = nr0 < N, bok1 = nr1 < N;
    const float* Br0 = Bm + (size_t)nr0 * K;
    const float* Br1 = Bm + (size_t)nr1 * K;
    const float4 z4 = make_float4(0.f, 0.f, 0.f, 0.f);

    const int nst = K >> 4;

    // Stage 0
    {
        float4 a0 = *(const float4*)(Ar0 + lq);
        float4 a1 = *(const float4*)(Ar1 + lq);
        float4 b0 = bok0 ? *(const float4*)(Br0 + lq) : z4;
        float4 b1 = bok1 ? *(const float4*)(Br1 + lq) : z4;
        *(uint4*)&As[0][lr     ][lq] = cvt4(a0);
        *(uint4*)&As[0][lr + 64][lq] = cvt4(a1);
        *(uint4*)&Bs[0][lr     ][lq] = cvt4(b0);
        *(uint4*)&Bs[0][lr + 64][lq] = cvt4(b1);
    }
    __syncthreads();

    float acc[2][8][4];
    #pragma unroll
    for (int i = 0; i < 2; i++)
        #pragma unroll
        for (int j = 0; j < 8; j++)
            #pragma unroll
            for (int q = 0; q < 4; q++) acc[i][j][q] = 0.f;

    for (int s = 0; s < nst; s++) {
        const int buf = s & 1;
        float4 na0, na1, nb0, nb1;
        const bool more = (s + 1 < nst);
        if (more) {
            const int ko = (s + 1) * 16 + lq;
            na0 = *(const float4*)(Ar0 + ko);
            na1 = *(const float4*)(Ar1 + ko);
            nb0 = bok0 ? *(const float4*)(Br0 + ko) : z4;
            nb1 = bok1 ? *(const float4*)(Br1 + ko) : z4;
        }

        #pragma unroll
        for (int kk = 0; kk < 16; kk += 8) {
            unsigned af[2][4];
            #pragma unroll
            for (int i = 0; i < 2; i++) {
                const int r = wm * 32 + i * 16 + gid;
                af[i][0] = As[buf][r    ][kk + tig];
                af[i][1] = As[buf][r + 8][kk + tig];
                af[i][2] = As[buf][r    ][kk + tig + 4];
                af[i][3] = As[buf][r + 8][kk + tig + 4];
            }
            #pragma unroll
            for (int j = 0; j < 8; j++) {
                unsigned bf[2];
                const int r = wn * 64 + j * 8 + gid;
                bf[0] = Bs[buf][r][kk + tig];
                bf[1] = Bs[buf][r][kk + tig + 4];
                mma_tf32(acc[0][j], af[0], bf);
                mma_tf32(acc[1][j], af[1], bf);
            }
        }

        if (more) {
            const int nb = buf ^ 1;
            *(uint4*)&As[nb][lr     ][lq] = cvt4(na0);
            *(uint4*)&As[nb][lr + 64][lq] = cvt4(na1);
            *(uint4*)&Bs[nb][lr     ][lq] = cvt4(nb0);
            *(uint4*)&Bs[nb][lr + 64][lq] = cvt4(nb1);
        }
        __syncthreads();
    }

    // Epilogue: c0/c1 -> (row, col..col+1), c2/c3 -> (row+8, ...)
    #pragma unroll
    for (int i = 0; i < 2; i++) {
        const int rg = bm + wm * 32 + i * 16 + gid;
        #pragma unroll
        for (int j = 0; j < 8; j++) {
            const int cg = bn + wn * 64 + j * 8 + tig * 2;
            if (cg < N) {
                const float2 bb = *(const float2*)&bias[cg];
                float2 c01 = make_float2(acc[i][j][0] + bb.x, acc[i][j][1] + bb.y);
                float2 c23 = make_float2(acc[i][j][2] + bb.x, acc[i][j][3] + bb.y);
                *(float2*)&C[(size_t)rg * ldc + cg]       = c01;
                *(float2*)&C[(size_t)(rg + 8) * ldc + cg] = c23;
            }
        }
    }
}

// h_final = [H0[T-1], H1[T-1]] -> d_out tail
__global__ void copy_final(const float* __restrict__ H0,
                           const float* __restrict__ H1,
                           float* __restrict__ dst)
{
    const int i = blockIdx.x * blockDim.x + threadIdx.x;
    if (i < BH)          dst[i] = H0[(size_t)(T_ - 1) * BH + i];
    else if (i < 2 * BH) dst[i] = H1[(size_t)(T_ - 1) * BH + (i - BH)];
}

extern "C" void kernel_launch(void* const* d_in, const int* in_sizes, int n_in,
                              void* d_out, int out_size)
{
    (void)in_sizes; (void)n_in; (void)out_size;
    const int*   inputs = (const int*)  d_in[0];   // [T, B]
    const float* hidden = (const float*)d_in[1];   // [L, B, H]
    const float* emb    = (const float*)d_in[2];   // [V, E]
    const float* Wx0    = (const float*)d_in[3];   // [H, E]
    const float* Wx1    = (const float*)d_in[4];   // [H, H]
    const float* Wh0    = (const float*)d_in[5];   // [H, H]
    const float* bh0    = (const float*)d_in[6];   // [H]
    const float* Wh1    = (const float*)d_in[7];   // [H, H]
    const float* bh1    = (const float*)d_in[8];   // [H]
    const float* Wy     = (const float*)d_in[9];   // [V, H]
    const float* by     = (const float*)d_in[10];  // [V]
    float* out = (float*)d_out;                    // [T*B*V][L*B*H]

    float *X0, *H0, *X1, *H1;
    cudaGetSymbolAddress((void**)&X0, g_X0);
    cudaGetSymbolAddress((void**)&H0, g_H0);
    cudaGetSymbolAddress((void**)&X1, g_X1);
    cudaGetSymbolAddress((void**)&H1, g_H1);

    // A: X0 = gather(emb) @ Wx0^T + bh0
    gemm_tf32<<<dim3(H_ / 128, MTOT / 128), 256>>>(emb, Wx0, bh0, X0, inputs, H_, E_, H_);

    // B: layer-0 recurrence (persistent, 70 steps, grid barriers)
    bar_init<<<1, 1>>>();
    rnn_layer<<<128, 256>>>(X0, hidden, Wh0, H0);

    // C: X1 = H0 @ Wx1^T + bh1
    gemm_tf32<<<dim3(H_ / 128, MTOT / 128), 256>>>(H0, Wx1, bh1, X1, nullptr, H_, H_, H_);

    // D: layer-1 recurrence
    bar_init<<<1, 1>>>();
    rnn_layer<<<128, 256>>>(X1, hidden + BH, Wh1, H1);

    // E: logits = H1 @ Wy^T + by
    gemm_tf32<<<dim3((V_ + 127) / 128, MTOT / 128), 256>>>(H1, Wy, by, out, nullptr, V_, H_, V_);

    // F: h_final tail
    copy_final<<<(2 * BH + 255) / 256, 256>>>(H0, H1, out + (size_t)MTOT * V_);
}